// round 4
// baseline (speedup 1.0000x reference)
#include <cuda_runtime.h>
#include <math.h>

#define NE 8
#define TOPK 2
#define DM 1024
#define DH 4096
#define T_TOK 4096
#define NPAIR (T_TOK*TOPK)
#define KS 32
#define ALD 36    // A smem row stride (words), [m][k32] layout
#define BLD 36    // B smem row stride (words), [n][k32] layout

// ---------------- scratch (device globals; no allocation) ----------------
__device__ int   g_count[NE];
__device__ int   g_off[NE];
__device__ int   g_cursor[NE];
__device__ int   g_pair_tok[NPAIR];
__device__ float g_pair_w[NPAIR];
__device__ int   g_tok_e[T_TOK*TOPK];
__device__ float g_tok_w[T_TOK*TOPK];
__device__ float g_act[(size_t)NPAIR*DH];     // tf32-rounded, k-permuted per 32-block
__device__ float g_w0T[(size_t)NE*DM*DH];     // [e][n=DH][k=DM], tf32, k-permuted
__device__ float g_w1T[(size_t)NE*DM*DH];
__device__ float g_w2T[(size_t)NE*DH*DM];     // [e][n=DM][k=DH]
__device__ float g_x[(size_t)T_TOK*DM];       // tf32, k-permuted

__device__ __forceinline__ unsigned f2tf(float f) {
    unsigned u;
    asm("cvt.rna.tf32.f32 %0, %1;" : "=r"(u) : "f"(f));
    return u;
}

__device__ __forceinline__ void mma_tf32(float c[4], unsigned a0, unsigned a1,
                                         unsigned a2, unsigned a3,
                                         unsigned b0, unsigned b1) {
    asm volatile(
        "mma.sync.aligned.m16n8k8.row.col.f32.tf32.tf32.f32 "
        "{%0,%1,%2,%3}, {%4,%5,%6,%7}, {%8,%9}, {%0,%1,%2,%3};\n"
        : "+f"(c[0]), "+f"(c[1]), "+f"(c[2]), "+f"(c[3])
        : "r"(a0), "r"(a1), "r"(a2), "r"(a3), "r"(b0), "r"(b1));
}

__device__ __forceinline__ unsigned sptr(const void* p) {
    return (unsigned)__cvta_generic_to_shared(p);
}
__device__ __forceinline__ void cp16(unsigned dst, const void* src, int srcbytes) {
    asm volatile("cp.async.cg.shared.global [%0], [%1], 16, %2;\n"
                 :: "r"(dst), "l"(src), "r"(srcbytes));
}
__device__ __forceinline__ void cp_commit() { asm volatile("cp.async.commit_group;\n"); }
__device__ __forceinline__ void cp_wait0()  { asm volatile("cp.async.wait_group 0;\n"); }

// ---------------- reset: zero output + counters ----------------
__global__ void k_reset(float* out, int n) {
    int i = blockIdx.x*blockDim.x + threadIdx.x;
    if (i < n) out[i] = 0.f;
    if (i < NE) g_count[i] = 0;
}

// ---------------- x prep: tf32 round + within-32 k-permutation ----------------
__global__ void k_cvtx(const float* __restrict__ in, float* __restrict__ outp, int n) {
    int i = blockIdx.x*blockDim.x + threadIdx.x;
    if (i < n) {
        int kl = i & 31;
        int j  = (i & ~31) + ((kl & 3) * 8) + (kl >> 2);
        outp[j] = __uint_as_float(f2tf(in[i]));
    }
}

// ---------------- weight prep: transpose [k][n]->[n][k], tf32, k-permuted ----------------
__global__ void k_tw(const float* __restrict__ in, float* __restrict__ outp,
                     int K, int N) {
    __shared__ float t[32][33];
    int e = blockIdx.z;
    const float* I = in + (size_t)e*K*N;
    float* O = outp + (size_t)e*N*K;
    int n0 = blockIdx.x*32, k0 = blockIdx.y*32;
    int tx = threadIdx.x, ty = threadIdx.y;
#pragma unroll
    for (int i = ty; i < 32; i += 8)
        t[i][tx] = I[(size_t)(k0+i)*N + n0 + tx];
    __syncthreads();
    int kl = (tx & 7)*4 + (tx >> 3);   // inverse permutation
#pragma unroll
    for (int j = ty; j < 32; j += 8)
        O[(size_t)(n0+j)*K + k0 + tx] = __uint_as_float(f2tf(t[kl][j]));
}

// ---------------- routing: logits, top-2, softmax ----------------
__global__ void k_route(const float* __restrict__ x,
                        const float* __restrict__ Wg,
                        const float* __restrict__ bg) {
    int t = blockIdx.x;
    int tid = threadIdx.x;
    const float* xr = x + (size_t)t*DM;
    float acc[NE];
#pragma unroll
    for (int e = 0; e < NE; e++) acc[e] = 0.f;
    for (int i = tid; i < DM; i += 256) {
        float xv = xr[i];
#pragma unroll
        for (int e = 0; e < NE; e++) acc[e] += xv * Wg[i*NE + e];
    }
    __shared__ float s[NE][256];
#pragma unroll
    for (int e = 0; e < NE; e++) s[e][tid] = acc[e];
    __syncthreads();
    for (int off = 128; off > 0; off >>= 1) {
        if (tid < off) {
#pragma unroll
            for (int e = 0; e < NE; e++) s[e][tid] += s[e][tid + off];
        }
        __syncthreads();
    }
    if (tid == 0) {
        float v[NE];
#pragma unroll
        for (int e = 0; e < NE; e++) v[e] = s[e][0] + bg[e];
        int i0 = 0;
#pragma unroll
        for (int e = 1; e < NE; e++) if (v[e] > v[i0]) i0 = e;
        int i1 = (i0 == 0) ? 1 : 0;
#pragma unroll
        for (int e = 0; e < NE; e++) if (e != i0 && v[e] > v[i1]) i1 = e;
        float e1 = expf(v[i1] - v[i0]);
        float inv = 1.f / (1.f + e1);
        g_tok_e[2*t]   = i0;  g_tok_w[2*t]   = inv;
        g_tok_e[2*t+1] = i1;  g_tok_w[2*t+1] = e1 * inv;
        atomicAdd(&g_count[i0], 1);
        atomicAdd(&g_count[i1], 1);
    }
}

__global__ void k_scan() {
    int o = 0;
    for (int e = 0; e < NE; e++) {
        g_off[e] = o;
        g_cursor[e] = o;
        o += g_count[e];
    }
}

__global__ void k_assign() {
    int t = blockIdx.x*blockDim.x + threadIdx.x;
    if (t >= T_TOK) return;
#pragma unroll
    for (int k = 0; k < TOPK; k++) {
        int e = g_tok_e[2*t + k];
        int pos = atomicAdd(&g_cursor[e], 1);
        g_pair_tok[pos] = t;
        g_pair_w[pos]   = g_tok_w[2*t + k];
    }
}

// ================= pass A: act = (x@W0+b0)*silu(x@W1+b1) =================
// block 128M x 64N, KS=32, 2-stage cp.async, fragment-ordered LDS.128
#define A1_WORDS (128*ALD)
#define B1_WORDS (64*BLD)
__global__ void __launch_bounds__(256) k_mlp1(const float* __restrict__ b0,
                                              const float* __restrict__ b1) {
    int e   = blockIdx.z;
    int cnt = g_count[e];
    int m0  = blockIdx.y * 128;
    if (m0 >= cnt) return;
    int off = g_off[e];
    int n0  = blockIdx.x * 64;

    const float* B0g = g_w0T + (size_t)e*DM*DH;   // [n=DH][k=DM]
    const float* B1g = g_w1T + (size_t)e*DM*DH;

    extern __shared__ float sm[];
    float* As  = sm;                    // [2][128][36]
    float* Bs0 = As + 2*A1_WORDS;       // [2][64][36]
    float* Bs1 = Bs0 + 2*B1_WORDS;
    int*  toks = (int*)(Bs1 + 2*B1_WORDS);

    int tid = threadIdx.x;
    if (tid < 128) {
        int m = m0 + tid;
        toks[tid] = (m < cnt) ? g_pair_tok[off + m] : -1;
    }
    __syncthreads();

    // A loader: 128 rows x 8 chunks
    int akb  = tid & 7;
    int arow = tid >> 3;
    const float* asrc[4]; int asz[4]; unsigned adst[4];
#pragma unroll
    for (int i = 0; i < 4; i++) {
        int r = arow + 32*i;
        int tok = toks[r];
        asrc[i] = g_x + (size_t)(tok < 0 ? 0 : tok)*DM + akb*4;
        asz[i]  = (tok < 0) ? 0 : 16;
        adst[i] = sptr(As + r*ALD + akb*4);
    }
    // B loader: 64 rows x 8 chunks; thread covers chunks c, c+4 of row tid>>2
    int bc  = tid & 3;
    int bnr = tid >> 2;
    const float* b0src = B0g + (size_t)(n0 + bnr)*DM + bc*4;
    const float* b1src = B1g + (size_t)(n0 + bnr)*DM + bc*4;
    unsigned b0dst = sptr(Bs0 + bnr*BLD + bc*4);
    unsigned b1dst = sptr(Bs1 + bnr*BLD + bc*4);

    int lane = tid & 31, warp = tid >> 5;
    int wm = warp & 3, wn = warp >> 2;
    int g  = lane >> 2, tig = lane & 3;

    float ch[2][4][4], cg[2][4][4];
#pragma unroll
    for (int mi = 0; mi < 2; mi++)
#pragma unroll
        for (int ni = 0; ni < 4; ni++)
#pragma unroll
            for (int j = 0; j < 4; j++) { ch[mi][ni][j] = 0.f; cg[mi][ni][j] = 0.f; }

#define LOAD_A1(stage, kk0)  {                                                    \
        unsigned soA = (stage)*A1_WORDS*4, soB = (stage)*B1_WORDS*4;              \
        _Pragma("unroll")                                                         \
        for (int i = 0; i < 4; i++) cp16(adst[i] + soA, asrc[i] + (kk0), asz[i]); \
        cp16(b0dst + soB,      b0src + (kk0),      16);                           \
        cp16(b0dst + soB + 64, b0src + (kk0) + 16, 16);                           \
        cp16(b1dst + soB,      b1src + (kk0),      16);                           \
        cp16(b1dst + soB + 64, b1src + (kk0) + 16, 16);                           \
        cp_commit(); }

    LOAD_A1(0, 0);

    const int NK = DM / KS;
    for (int kt = 0; kt < NK; kt++) {
        int cur = kt & 1;
        cp_wait0();
        __syncthreads();
        if (kt + 1 < NK) LOAD_A1(cur ^ 1, (kt + 1)*KS);

        const float* Ac  = As  + cur*A1_WORDS;
        const float* B0c = Bs0 + cur*B1_WORDS;
        const float* B1c = Bs1 + cur*B1_WORDS;

        // A fragments: 8 contiguous floats per (mi, row-half)
        float Aa[2][2][8];
#pragma unroll
        for (int mi = 0; mi < 2; mi++)
#pragma unroll
            for (int rr = 0; rr < 2; rr++) {
                int m = wm*32 + mi*16 + rr*8 + g;
                float4 v0 = *(const float4*)&Ac[m*ALD + tig*8];
                float4 v1 = *(const float4*)&Ac[m*ALD + tig*8 + 4];
                Aa[mi][rr][0]=v0.x; Aa[mi][rr][1]=v0.y; Aa[mi][rr][2]=v0.z; Aa[mi][rr][3]=v0.w;
                Aa[mi][rr][4]=v1.x; Aa[mi][rr][5]=v1.y; Aa[mi][rr][6]=v1.z; Aa[mi][rr][7]=v1.w;
            }
#pragma unroll
        for (int ni = 0; ni < 4; ni++) {
            int n = wn*32 + ni*8 + g;
            float4 p0 = *(const float4*)&B0c[n*BLD + tig*8];
            float4 p1 = *(const float4*)&B0c[n*BLD + tig*8 + 4];
            float4 q0 = *(const float4*)&B1c[n*BLD + tig*8];
            float4 q1 = *(const float4*)&B1c[n*BLD + tig*8 + 4];
            float bp[8] = {p0.x,p0.y,p0.z,p0.w,p1.x,p1.y,p1.z,p1.w};
            float bq[8] = {q0.x,q0.y,q0.z,q0.w,q1.x,q1.y,q1.z,q1.w};
#pragma unroll
            for (int j = 0; j < 4; j++) {
                unsigned bb0 = __float_as_uint(bp[2*j]), bb1 = __float_as_uint(bp[2*j+1]);
                unsigned cc0 = __float_as_uint(bq[2*j]), cc1 = __float_as_uint(bq[2*j+1]);
#pragma unroll
                for (int mi = 0; mi < 2; mi++) {
                    unsigned a0 = __float_as_uint(Aa[mi][0][2*j]);
                    unsigned a1 = __float_as_uint(Aa[mi][1][2*j]);
                    unsigned a2 = __float_as_uint(Aa[mi][0][2*j+1]);
                    unsigned a3 = __float_as_uint(Aa[mi][1][2*j+1]);
                    mma_tf32(ch[mi][ni], a0,a1,a2,a3, bb0, bb1);
                    mma_tf32(cg[mi][ni], a0,a1,a2,a3, cc0, cc1);
                }
            }
        }
        __syncthreads();
    }

    const float* b0p = b0 + (size_t)e*DH;
    const float* b1p = b1 + (size_t)e*DH;
#pragma unroll
    for (int mi = 0; mi < 2; mi++) {
#pragma unroll
        for (int hh = 0; hh < 2; hh++) {
            int r = m0 + wm*32 + mi*16 + g + hh*8;
            if (r < cnt) {
                size_t row = (size_t)(off + r);
#pragma unroll
                for (int ni = 0; ni < 4; ni++) {
                    int c  = n0 + wn*32 + ni*8 + tig*2;
                    int kl = c & 31;
                    int cp_ = (c & ~31) + ((kl & 3)*8) + (kl >> 2);
                    float h0 = ch[mi][ni][hh*2+0] + b0p[c];
                    float g0 = cg[mi][ni][hh*2+0] + b1p[c];
                    float h1 = ch[mi][ni][hh*2+1] + b0p[c+1];
                    float g1 = cg[mi][ni][hh*2+1] + b1p[c+1];
                    g_act[row*DH + cp_    ] = __uint_as_float(f2tf(h0 * (g0 / (1.f + expf(-g0)))));
                    g_act[row*DH + cp_ + 8] = __uint_as_float(f2tf(h1 * (g1 / (1.f + expf(-g1)))));
                }
            }
        }
    }
}

// ================= pass B: out[token] += w * (act @ W2 + b2) =================
__global__ void __launch_bounds__(256,2) k_mlp2(const float* __restrict__ b2,
                                                float* __restrict__ out) {
    int e   = blockIdx.z;
    int cnt = g_count[e];
    int m0  = blockIdx.y * 128;
    if (m0 >= cnt) return;
    int off = g_off[e];
    int n0  = blockIdx.x * 64;

    const float* Bg = g_w2T + (size_t)e*DH*DM;   // [n=DM][k=DH]

    extern __shared__ float sm[];
    float* As = sm;                  // [2][128][36]
    float* Bs = As + 2*A1_WORDS;     // [2][64][36]

    int tid = threadIdx.x;

    int akb  = tid & 7;
    int arow = tid >> 3;
    const float* asrc[4]; int asz[4]; unsigned adst[4];
#pragma unroll
    for (int i = 0; i < 4; i++) {
        int r = arow + 32*i;
        int m = m0 + r;
        int ok = (m < cnt);
        asrc[i] = g_act + (size_t)(ok ? (off + m) : 0)*DH + akb*4;
        asz[i]  = ok ? 16 : 0;
        adst[i] = sptr(As + r*ALD + akb*4);
    }
    int bc  = tid & 3;
    int bnr = tid >> 2;
    const float* bsrc = Bg + (size_t)(n0 + bnr)*DH + bc*4;
    unsigned bdst = sptr(Bs + bnr*BLD + bc*4);

    int lane = tid & 31, warp = tid >> 5;
    int wm = warp & 3, wn = warp >> 2;
    int g  = lane >> 2, tig = lane & 3;

    float acc[2][4][4];
#pragma unroll
    for (int mi = 0; mi < 2; mi++)
#pragma unroll
        for (int ni = 0; ni < 4; ni++)
#pragma unroll
            for (int j = 0; j < 4; j++) acc[mi][ni][j] = 0.f;

#define LOAD_B1(stage, kk0)  {                                                    \
        unsigned soA = (stage)*A1_WORDS*4, soB = (stage)*B1_WORDS*4;              \
        _Pragma("unroll")                                                         \
        for (int i = 0; i < 4; i++) cp16(adst[i] + soA, asrc[i] + (kk0), asz[i]); \
        cp16(bdst + soB,      bsrc + (kk0),      16);                             \
        cp16(bdst + soB + 64, bsrc + (kk0) + 16, 16);                             \
        cp_commit(); }

    LOAD_B1(0, 0);

    const int NK = DH / KS;
    for (int kt = 0; kt < NK; kt++) {
        int cur = kt & 1;
        cp_wait0();
        __syncthreads();
        if (kt + 1 < NK) LOAD_B1(cur ^ 1, (kt + 1)*KS);

        const float* Ac = As + cur*A1_WORDS;
        const float* Bc = Bs + cur*B1_WORDS;

        float Aa[2][2][8];
#pragma unroll
        for (int mi = 0; mi < 2; mi++)
#pragma unroll
            for (int rr = 0; rr < 2; rr++) {
                int m = wm*32 + mi*16 + rr*8 + g;
                float4 v0 = *(const float4*)&Ac[m*ALD + tig*8];
                float4 v1 = *(const float4*)&Ac[m*ALD + tig*8 + 4];
                Aa[mi][rr][0]=v0.x; Aa[mi][rr][1]=v0.y; Aa[mi][rr][2]=v0.z; Aa[mi][rr][3]=v0.w;
                Aa[mi][rr][4]=v1.x; Aa[mi][rr][5]=v1.y; Aa[mi][rr][6]=v1.z; Aa[mi][rr][7]=v1.w;
            }
#pragma unroll
        for (int ni = 0; ni < 4; ni++) {
            int n = wn*32 + ni*8 + g;
            float4 p0 = *(const float4*)&Bc[n*BLD + tig*8];
            float4 p1 = *(const float4*)&Bc[n*BLD + tig*8 + 4];
            float bp[8] = {p0.x,p0.y,p0.z,p0.w,p1.x,p1.y,p1.z,p1.w};
#pragma unroll
            for (int j = 0; j < 4; j++) {
                unsigned bb0 = __float_as_uint(bp[2*j]), bb1 = __float_as_uint(bp[2*j+1]);
#pragma unroll
                for (int mi = 0; mi < 2; mi++) {
                    unsigned a0 = __float_as_uint(Aa[mi][0][2*j]);
                    unsigned a1 = __float_as_uint(Aa[mi][1][2*j]);
                    unsigned a2 = __float_as_uint(Aa[mi][0][2*j+1]);
                    unsigned a3 = __float_as_uint(Aa[mi][1][2*j+1]);
                    mma_tf32(acc[mi][ni], a0,a1,a2,a3, bb0, bb1);
                }
            }
        }
        __syncthreads();
    }

    const float* b2p = b2 + (size_t)e*DM;
#pragma unroll
    for (int mi = 0; mi < 2; mi++) {
#pragma unroll
        for (int hh = 0; hh < 2; hh++) {
            int r = m0 + wm*32 + mi*16 + g + hh*8;
            if (r < cnt) {
                int tok = g_pair_tok[off + r];
                float w = g_pair_w[off + r];
                float* orow = out + (size_t)tok*DM;
#pragma unroll
                for (int ni = 0; ni < 4; ni++) {
                    int c = n0 + wn*32 + ni*8 + tig*2;
                    atomicAdd(&orow[c],   w * (acc[mi][ni][hh*2+0] + b2p[c]));
                    atomicAdd(&orow[c+1], w * (acc[mi][ni][hh*2+1] + b2p[c+1]));
                }
            }
        }
    }
}

// ---------------- launch ----------------
#define SMEM_MLP1 ((2*A1_WORDS + 4*B1_WORDS)*4 + 128*4)
#define SMEM_MLP2 ((2*A1_WORDS + 2*B1_WORDS)*4)

extern "C" void kernel_launch(void* const* d_in, const int* in_sizes, int n_in,
                              void* d_out, int out_size) {
    const float* x  = (const float*)d_in[0];
    const float* Wg = (const float*)d_in[1];
    const float* bg = (const float*)d_in[2];
    const float* W0 = (const float*)d_in[3];
    const float* b0 = (const float*)d_in[4];
    const float* W1 = (const float*)d_in[5];
    const float* b1 = (const float*)d_in[6];
    const float* W2 = (const float*)d_in[7];
    const float* b2 = (const float*)d_in[8];
    float* out = (float*)d_out;

    static int smem_set = 0;
    if (!smem_set) {
        cudaFuncSetAttribute(k_mlp1, cudaFuncAttributeMaxDynamicSharedMemorySize, SMEM_MLP1);
        cudaFuncSetAttribute(k_mlp2, cudaFuncAttributeMaxDynamicSharedMemorySize, SMEM_MLP2);
        smem_set = 1;
    }

    float* w0d; cudaGetSymbolAddress((void**)&w0d, g_w0T);
    float* w1d; cudaGetSymbolAddress((void**)&w1d, g_w1T);
    float* w2d; cudaGetSymbolAddress((void**)&w2d, g_w2T);
    float* xd;  cudaGetSymbolAddress((void**)&xd,  g_x);

    const int XN = T_TOK*DM;

    k_reset <<<(T_TOK*DM + 255)/256, 256>>>(out, T_TOK*DM);
    k_route <<<T_TOK, 256>>>(x, Wg, bg);
    k_scan  <<<1, 1>>>();
    k_assign<<<(T_TOK + 255)/256, 256>>>();
    k_cvtx  <<<(XN + 255)/256, 256>>>(x, xd, XN);
    k_tw    <<<dim3(DH/32, DM/32, NE), dim3(32,8)>>>(W0, w0d, DM, DH);
    k_tw    <<<dim3(DH/32, DM/32, NE), dim3(32,8)>>>(W1, w1d, DM, DH);
    k_tw    <<<dim3(DM/32, DH/32, NE), dim3(32,8)>>>(W2, w2d, DH, DM);
    k_mlp1  <<<dim3(DH/64, 32, NE), 256, SMEM_MLP1>>>(b0, b1);
    k_mlp2  <<<dim3(DM/64, 32, NE), 256, SMEM_MLP2>>>(b2, out);
}

// round 5
// speedup vs baseline: 1.5887x; 1.5887x over previous
#include <cuda_runtime.h>
#include <cuda_fp16.h>
#include <math.h>

#define NE 8
#define TOPK 2
#define DM 1024
#define DH 4096
#define T_TOK 4096
#define NPAIR (T_TOK*TOPK)
#define KS 32          // k-tile in elements (halfs)
#define HLD 40         // smem row stride in halfs (padded)
#define TILE_H (128*HLD)   // halfs per tile buffer

// ---------------- scratch (device globals; no allocation) ----------------
__device__ int    g_count[NE];
__device__ int    g_off[NE];
__device__ int    g_cursor[NE];
__device__ int    g_pair_tok[NPAIR];
__device__ float  g_pair_w[NPAIR];
__device__ int    g_tok_e[T_TOK*TOPK];
__device__ float  g_tok_w[T_TOK*TOPK];
__device__ __half g_acth[(size_t)NPAIR*DH];    // 64 MB fp16 activations
__device__ __half g_w0h[(size_t)NE*DM*DH];     // [e][n=DH][k=DM] fp16 transposed
__device__ __half g_w1h[(size_t)NE*DM*DH];
__device__ __half g_w2h[(size_t)NE*DH*DM];     // [e][n=DM][k=DH]
__device__ __half g_xh[(size_t)T_TOK*DM];      // fp16 activations

__device__ __forceinline__ void mma_f16(float c[4], unsigned a0, unsigned a1,
                                        unsigned a2, unsigned a3,
                                        unsigned b0, unsigned b1) {
    asm volatile(
        "mma.sync.aligned.m16n8k16.row.col.f32.f16.f16.f32 "
        "{%0,%1,%2,%3}, {%4,%5,%6,%7}, {%8,%9}, {%0,%1,%2,%3};\n"
        : "+f"(c[0]), "+f"(c[1]), "+f"(c[2]), "+f"(c[3])
        : "r"(a0), "r"(a1), "r"(a2), "r"(a3), "r"(b0), "r"(b1));
}

__device__ __forceinline__ unsigned sptr(const void* p) {
    return (unsigned)__cvta_generic_to_shared(p);
}
__device__ __forceinline__ void cp16(unsigned dst, const void* src, int srcbytes) {
    asm volatile("cp.async.cg.shared.global [%0], [%1], 16, %2;\n"
                 :: "r"(dst), "l"(src), "r"(srcbytes));
}
__device__ __forceinline__ void cp_commit() { asm volatile("cp.async.commit_group;\n"); }
__device__ __forceinline__ void cp_wait0()  { asm volatile("cp.async.wait_group 0;\n"); }

// ---------------- reset: zero output + counters ----------------
__global__ void k_reset(float* out, int n) {
    int i = blockIdx.x*blockDim.x + threadIdx.x;
    if (i < n) out[i] = 0.f;
    if (i < NE) g_count[i] = 0;
}

// ---------------- x -> fp16 ----------------
__global__ void k_cvtx(const float* __restrict__ in, __half* __restrict__ outp, int n4) {
    int i = blockIdx.x*blockDim.x + threadIdx.x;
    if (i < n4) {
        float4 v = ((const float4*)in)[i];
        __half2 a = __floats2half2_rn(v.x, v.y);
        __half2 b = __floats2half2_rn(v.z, v.w);
        ((__half2*)outp)[2*i]   = a;
        ((__half2*)outp)[2*i+1] = b;
    }
}

// ---------------- weight prep: transpose [k][n] -> [n][k], fp16 ----------------
__global__ void k_tw(const float* __restrict__ in, __half* __restrict__ outp,
                     int K, int N) {
    __shared__ float t[32][33];
    int e = blockIdx.z;
    const float* I = in + (size_t)e*K*N;
    __half* O = outp + (size_t)e*N*K;
    int n0 = blockIdx.x*32, k0 = blockIdx.y*32;
    int tx = threadIdx.x, ty = threadIdx.y;
#pragma unroll
    for (int i = ty; i < 32; i += 8)
        t[i][tx] = I[(size_t)(k0+i)*N + n0 + tx];
    __syncthreads();
#pragma unroll
    for (int j = ty; j < 32; j += 8)
        O[(size_t)(n0+j)*K + k0 + tx] = __float2half(t[tx][j]);
}

// ---------------- routing: logits, top-2, softmax (fp32 exact) ----------------
__global__ void k_route(const float* __restrict__ x,
                        const float* __restrict__ Wg,
                        const float* __restrict__ bg) {
    int t = blockIdx.x;
    int tid = threadIdx.x;
    const float* xr = x + (size_t)t*DM;
    float acc[NE];
#pragma unroll
    for (int e = 0; e < NE; e++) acc[e] = 0.f;
    for (int i = tid; i < DM; i += 256) {
        float xv = xr[i];
#pragma unroll
        for (int e = 0; e < NE; e++) acc[e] += xv * Wg[i*NE + e];
    }
    __shared__ float s[NE][256];
#pragma unroll
    for (int e = 0; e < NE; e++) s[e][tid] = acc[e];
    __syncthreads();
    for (int off = 128; off > 0; off >>= 1) {
        if (tid < off) {
#pragma unroll
            for (int e = 0; e < NE; e++) s[e][tid] += s[e][tid + off];
        }
        __syncthreads();
    }
    if (tid == 0) {
        float v[NE];
#pragma unroll
        for (int e = 0; e < NE; e++) v[e] = s[e][0] + bg[e];
        int i0 = 0;
#pragma unroll
        for (int e = 1; e < NE; e++) if (v[e] > v[i0]) i0 = e;
        int i1 = (i0 == 0) ? 1 : 0;
#pragma unroll
        for (int e = 0; e < NE; e++) if (e != i0 && v[e] > v[i1]) i1 = e;
        float e1 = expf(v[i1] - v[i0]);
        float inv = 1.f / (1.f + e1);
        g_tok_e[2*t]   = i0;  g_tok_w[2*t]   = inv;
        g_tok_e[2*t+1] = i1;  g_tok_w[2*t+1] = e1 * inv;
        atomicAdd(&g_count[i0], 1);
        atomicAdd(&g_count[i1], 1);
    }
}

__global__ void k_scan() {
    int o = 0;
    for (int e = 0; e < NE; e++) {
        g_off[e] = o;
        g_cursor[e] = o;
        o += g_count[e];
    }
}

__global__ void k_assign() {
    int t = blockIdx.x*blockDim.x + threadIdx.x;
    if (t >= T_TOK) return;
#pragma unroll
    for (int k = 0; k < TOPK; k++) {
        int e = g_tok_e[2*t + k];
        int pos = atomicAdd(&g_cursor[e], 1);
        g_pair_tok[pos] = t;
        g_pair_w[pos]   = g_tok_w[2*t + k];
    }
}

// ================= pass A: act = (x@W0+b0)*silu(x@W1+b1) =================
// block 128M x 128N, KS=32, 2-stage cp.async, fp16 m16n8k16.
// 512 threads = 16 warps (4x4), warp tile 32x32.
__global__ void __launch_bounds__(512,1) k_mlp1(const float* __restrict__ b0,
                                                const float* __restrict__ b1) {
    int e   = blockIdx.z;
    int cnt = g_count[e];
    int m0  = blockIdx.y * 128;
    if (m0 >= cnt) return;
    int off = g_off[e];
    int n0  = blockIdx.x * 128;

    const __half* B0g = g_w0h + (size_t)e*DM*DH;   // [n][k]
    const __half* B1g = g_w1h + (size_t)e*DM*DH;

    extern __shared__ __half sh[];
    __half* As  = sh;                    // [2][128][40]
    __half* Bs0 = As + 2*TILE_H;
    __half* Bs1 = Bs0 + 2*TILE_H;
    int*  toks = (int*)(Bs1 + 2*TILE_H);

    int tid = threadIdx.x;
    if (tid < 128) {
        int m = m0 + tid;
        toks[tid] = (m < cnt) ? g_pair_tok[off + m] : -1;
    }
    __syncthreads();

    // loaders: 128 rows x 4 chunks of 8 halfs; one (row,chunk) per thread
    int lrow = tid >> 2;
    int lch  = (tid & 3) * 8;
    int tok  = toks[lrow];
    const __half* asrc = g_xh + (size_t)(tok < 0 ? 0 : tok)*DM + lch;
    int asz = (tok < 0) ? 0 : 16;
    unsigned adst = sptr(As + lrow*HLD + lch);
    const __half* b0src = B0g + (size_t)(n0 + lrow)*DM + lch;
    const __half* b1src = B1g + (size_t)(n0 + lrow)*DM + lch;
    unsigned b0dst = sptr(Bs0 + lrow*HLD + lch);
    unsigned b1dst = sptr(Bs1 + lrow*HLD + lch);

    int lane = tid & 31, warp = tid >> 5;
    int wm = warp & 3, wn = warp >> 2;
    int g  = lane >> 2, tig = lane & 3;

    float ch[2][4][4], cg[2][4][4];
#pragma unroll
    for (int mi = 0; mi < 2; mi++)
#pragma unroll
        for (int ni = 0; ni < 4; ni++)
#pragma unroll
            for (int j = 0; j < 4; j++) { ch[mi][ni][j] = 0.f; cg[mi][ni][j] = 0.f; }

#define LOAD1(stage, kk0)  {                              \
        unsigned so = (stage)*TILE_H*2;                   \
        cp16(adst  + so, asrc  + (kk0), asz);             \
        cp16(b0dst + so, b0src + (kk0), 16);              \
        cp16(b1dst + so, b1src + (kk0), 16);              \
        cp_commit(); }

    LOAD1(0, 0);

    const int NK = DM / KS;
    for (int kt = 0; kt < NK; kt++) {
        int cur = kt & 1;
        cp_wait0();
        __syncthreads();
        if (kt + 1 < NK) LOAD1(cur ^ 1, (kt + 1)*KS);

        const __half* Ac  = As  + cur*TILE_H;
        const __half* B0c = Bs0 + cur*TILE_H;
        const __half* B1c = Bs1 + cur*TILE_H;

#pragma unroll
        for (int ks = 0; ks < KS; ks += 16) {
            unsigned a[2][4];
#pragma unroll
            for (int mi = 0; mi < 2; mi++) {
                int m = wm*32 + mi*16 + g;
                a[mi][0] = *(const unsigned*)&Ac[(m  )*HLD + ks + 2*tig    ];
                a[mi][1] = *(const unsigned*)&Ac[(m+8)*HLD + ks + 2*tig    ];
                a[mi][2] = *(const unsigned*)&Ac[(m  )*HLD + ks + 2*tig + 8];
                a[mi][3] = *(const unsigned*)&Ac[(m+8)*HLD + ks + 2*tig + 8];
            }
#pragma unroll
            for (int ni = 0; ni < 4; ni++) {
                int n = wn*32 + ni*8 + g;
                unsigned p0 = *(const unsigned*)&B0c[n*HLD + ks + 2*tig    ];
                unsigned p1 = *(const unsigned*)&B0c[n*HLD + ks + 2*tig + 8];
                unsigned q0 = *(const unsigned*)&B1c[n*HLD + ks + 2*tig    ];
                unsigned q1 = *(const unsigned*)&B1c[n*HLD + ks + 2*tig + 8];
#pragma unroll
                for (int mi = 0; mi < 2; mi++) {
                    mma_f16(ch[mi][ni], a[mi][0],a[mi][1],a[mi][2],a[mi][3], p0, p1);
                    mma_f16(cg[mi][ni], a[mi][0],a[mi][1],a[mi][2],a[mi][3], q0, q1);
                }
            }
        }
        __syncthreads();
    }

    const float* b0p = b0 + (size_t)e*DH;
    const float* b1p = b1 + (size_t)e*DH;
#pragma unroll
    for (int mi = 0; mi < 2; mi++) {
#pragma unroll
        for (int hh = 0; hh < 2; hh++) {
            int r = m0 + wm*32 + mi*16 + g + hh*8;
            if (r < cnt) {
                size_t row = (size_t)(off + r);
#pragma unroll
                for (int ni = 0; ni < 4; ni++) {
                    int c = n0 + wn*32 + ni*8 + tig*2;
                    float h0 = ch[mi][ni][hh*2+0] + b0p[c];
                    float g0 = cg[mi][ni][hh*2+0] + b1p[c];
                    float h1 = ch[mi][ni][hh*2+1] + b0p[c+1];
                    float g1 = cg[mi][ni][hh*2+1] + b1p[c+1];
                    float o0 = h0 * (g0 / (1.f + expf(-g0)));
                    float o1 = h1 * (g1 / (1.f + expf(-g1)));
                    *(__half2*)&g_acth[row*DH + c] = __floats2half2_rn(o0, o1);
                }
            }
        }
    }
}

// ================= pass B: out[token] += w * (act @ W2 + b2) =================
__global__ void __launch_bounds__(512,1) k_mlp2(const float* __restrict__ b2,
                                                float* __restrict__ out) {
    int e   = blockIdx.z;
    int cnt = g_count[e];
    int m0  = blockIdx.y * 128;
    if (m0 >= cnt) return;
    int off = g_off[e];
    int n0  = blockIdx.x * 128;

    const __half* Bg = g_w2h + (size_t)e*DH*DM;   // [n][k]

    extern __shared__ __half sh[];
    __half* As = sh;                  // [2][128][40]
    __half* Bs = As + 2*TILE_H;

    int tid = threadIdx.x;
    int lrow = tid >> 2;
    int lch  = (tid & 3) * 8;
    int m = m0 + lrow;
    int ok = (m < cnt);
    const __half* asrc = g_acth + (size_t)(ok ? (off + m) : 0)*DH + lch;
    int asz = ok ? 16 : 0;
    unsigned adst = sptr(As + lrow*HLD + lch);
    const __half* bsrc = Bg + (size_t)(n0 + lrow)*DH + lch;
    unsigned bdst = sptr(Bs + lrow*HLD + lch);

    int lane = tid & 31, warp = tid >> 5;
    int wm = warp & 3, wn = warp >> 2;
    int g  = lane >> 2, tig = lane & 3;

    float acc[2][4][4];
#pragma unroll
    for (int mi = 0; mi < 2; mi++)
#pragma unroll
        for (int ni = 0; ni < 4; ni++)
#pragma unroll
            for (int j = 0; j < 4; j++) acc[mi][ni][j] = 0.f;

#define LOAD2(stage, kk0)  {                              \
        unsigned so = (stage)*TILE_H*2;                   \
        cp16(adst + so, asrc + (kk0), asz);               \
        cp16(bdst + so, bsrc + (kk0), 16);                \
        cp_commit(); }

    LOAD2(0, 0);

    const int NK = DH / KS;
    for (int kt = 0; kt < NK; kt++) {
        int cur = kt & 1;
        cp_wait0();
        __syncthreads();
        if (kt + 1 < NK) LOAD2(cur ^ 1, (kt + 1)*KS);

        const __half* Ac = As + cur*TILE_H;
        const __half* Bc = Bs + cur*TILE_H;

#pragma unroll
        for (int ks = 0; ks < KS; ks += 16) {
            unsigned a[2][4];
#pragma unroll
            for (int mi = 0; mi < 2; mi++) {
                int mm = wm*32 + mi*16 + g;
                a[mi][0] = *(const unsigned*)&Ac[(mm  )*HLD + ks + 2*tig    ];
                a[mi][1] = *(const unsigned*)&Ac[(mm+8)*HLD + ks + 2*tig    ];
                a[mi][2] = *(const unsigned*)&Ac[(mm  )*HLD + ks + 2*tig + 8];
                a[mi][3] = *(const unsigned*)&Ac[(mm+8)*HLD + ks + 2*tig + 8];
            }
#pragma unroll
            for (int ni = 0; ni < 4; ni++) {
                int n = wn*32 + ni*8 + g;
                unsigned p0 = *(const unsigned*)&Bc[n*HLD + ks + 2*tig    ];
                unsigned p1 = *(const unsigned*)&Bc[n*HLD + ks + 2*tig + 8];
#pragma unroll
                for (int mi = 0; mi < 2; mi++) {
                    mma_f16(acc[mi][ni], a[mi][0],a[mi][1],a[mi][2],a[mi][3], p0, p1);
                }
            }
        }
        __syncthreads();
    }

    const float* b2p = b2 + (size_t)e*DM;
#pragma unroll
    for (int mi = 0; mi < 2; mi++) {
#pragma unroll
        for (int hh = 0; hh < 2; hh++) {
            int r = m0 + wm*32 + mi*16 + g + hh*8;
            if (r < cnt) {
                int tokp = g_pair_tok[off + r];
                float w = g_pair_w[off + r];
                float* orow = out + (size_t)tokp*DM;
#pragma unroll
                for (int ni = 0; ni < 4; ni++) {
                    int c = n0 + wn*32 + ni*8 + tig*2;
                    atomicAdd(&orow[c],   w * (acc[mi][ni][hh*2+0] + b2p[c]));
                    atomicAdd(&orow[c+1], w * (acc[mi][ni][hh*2+1] + b2p[c+1]));
                }
            }
        }
    }
}

// ---------------- launch ----------------
#define SMEM1 (3*2*TILE_H*2 + 128*4)
#define SMEM2 (2*2*TILE_H*2)

extern "C" void kernel_launch(void* const* d_in, const int* in_sizes, int n_in,
                              void* d_out, int out_size) {
    const float* x  = (const float*)d_in[0];
    const float* Wg = (const float*)d_in[1];
    const float* bg = (const float*)d_in[2];
    const float* W0 = (const float*)d_in[3];
    const float* b0 = (const float*)d_in[4];
    const float* W1 = (const float*)d_in[5];
    const float* b1 = (const float*)d_in[6];
    const float* W2 = (const float*)d_in[7];
    const float* b2 = (const float*)d_in[8];
    float* out = (float*)d_out;

    static int smem_set = 0;
    if (!smem_set) {
        cudaFuncSetAttribute(k_mlp1, cudaFuncAttributeMaxDynamicSharedMemorySize, SMEM1);
        cudaFuncSetAttribute(k_mlp2, cudaFuncAttributeMaxDynamicSharedMemorySize, SMEM2);
        smem_set = 1;
    }

    __half* w0d; cudaGetSymbolAddress((void**)&w0d, g_w0h);
    __half* w1d; cudaGetSymbolAddress((void**)&w1d, g_w1h);
    __half* w2d; cudaGetSymbolAddress((void**)&w2d, g_w2h);
    __half* xd;  cudaGetSymbolAddress((void**)&xd,  g_xh);

    const int XN4 = T_TOK*DM/4;

    k_reset <<<(T_TOK*DM + 255)/256, 256>>>(out, T_TOK*DM);
    k_route <<<T_TOK, 256>>>(x, Wg, bg);
    k_scan  <<<1, 1>>>();
    k_assign<<<(T_TOK + 255)/256, 256>>>();
    k_cvtx  <<<(XN4 + 255)/256, 256>>>(x, xd, XN4);
    k_tw    <<<dim3(DH/32, DM/32, NE), dim3(32,8)>>>(W0, w0d, DM, DH);
    k_tw    <<<dim3(DH/32, DM/32, NE), dim3(32,8)>>>(W1, w1d, DM, DH);
    k_tw    <<<dim3(DM/32, DH/32, NE), dim3(32,8)>>>(W2, w2d, DH, DM);
    k_mlp1  <<<dim3(DH/128, 32, NE), 512, SMEM1>>>(b0, b1);
    k_mlp2  <<<dim3(DM/128, 32, NE), 512, SMEM2>>>(b2, out);
}

// round 7
// speedup vs baseline: 1.8348x; 1.1549x over previous
#include <cuda_runtime.h>
#include <cuda_fp16.h>
#include <math.h>

#define NE 8
#define TOPK 2
#define DM 1024
#define DH 4096
#define T_TOK 4096
#define NPAIR (T_TOK*TOPK)
#define KS 32          // k-tile in elements (halfs)
#define HLD 40         // smem row stride in halfs (padded)
#define TILE_H (128*HLD)   // halfs per tile buffer

// ---------------- scratch (device globals; no allocation) ----------------
__device__ int    g_count[NE];
__device__ int    g_off[NE];
__device__ int    g_cursor[NE];
__device__ int    g_pair_tok[NPAIR];
__device__ float  g_pair_w[NPAIR];
__device__ int    g_tok_e[T_TOK*TOPK];
__device__ float  g_tok_w[T_TOK*TOPK];
__device__ __half g_acth[(size_t)NPAIR*DH];    // 64 MB fp16 activations
__device__ __half g_w0h[(size_t)NE*DM*DH];     // [e][n=DH][k=DM] fp16 transposed
__device__ __half g_w1h[(size_t)NE*DM*DH];
__device__ __half g_w2h[(size_t)NE*DH*DM];     // [e][n=DM][k=DH]
__device__ __half g_xh[(size_t)T_TOK*DM];      // fp16 activations

__device__ __forceinline__ void mma_f16(float c[4], unsigned a0, unsigned a1,
                                        unsigned a2, unsigned a3,
                                        unsigned b0, unsigned b1) {
    asm volatile(
        "mma.sync.aligned.m16n8k16.row.col.f32.f16.f16.f32 "
        "{%0,%1,%2,%3}, {%4,%5,%6,%7}, {%8,%9}, {%0,%1,%2,%3};\n"
        : "+f"(c[0]), "+f"(c[1]), "+f"(c[2]), "+f"(c[3])
        : "r"(a0), "r"(a1), "r"(a2), "r"(a3), "r"(b0), "r"(b1));
}

__device__ __forceinline__ void ldsm4(unsigned r[4], unsigned addr) {
    asm volatile("ldmatrix.sync.aligned.m8n8.x4.shared.b16 {%0,%1,%2,%3}, [%4];"
                 : "=r"(r[0]), "=r"(r[1]), "=r"(r[2]), "=r"(r[3]) : "r"(addr));
}

__device__ __forceinline__ unsigned sptr(const void* p) {
    return (unsigned)__cvta_generic_to_shared(p);
}
__device__ __forceinline__ void cp16(unsigned dst, const void* src, int srcbytes) {
    asm volatile("cp.async.cg.shared.global [%0], [%1], 16, %2;\n"
                 :: "r"(dst), "l"(src), "r"(srcbytes));
}
__device__ __forceinline__ void cp_commit() { asm volatile("cp.async.commit_group;\n"); }
__device__ __forceinline__ void cp_wait0()  { asm volatile("cp.async.wait_group 0;\n"); }

// ---------------- reset: zero output + counters ----------------
__global__ void k_reset(float* out, int n) {
    int i = blockIdx.x*blockDim.x + threadIdx.x;
    if (i < n) out[i] = 0.f;
    if (i < NE) g_count[i] = 0;
}

// ---------------- x -> fp16 ----------------
__global__ void k_cvtx(const float* __restrict__ in, __half* __restrict__ outp, int n4) {
    int i = blockIdx.x*blockDim.x + threadIdx.x;
    if (i < n4) {
        float4 v = ((const float4*)in)[i];
        ((__half2*)outp)[2*i]   = __floats2half2_rn(v.x, v.y);
        ((__half2*)outp)[2*i+1] = __floats2half2_rn(v.z, v.w);
    }
}

// ---------------- weight prep: transpose [k][n] -> [n][k], fp16 ----------------
__global__ void k_tw(const float* __restrict__ in, __half* __restrict__ outp,
                     int K, int N) {
    __shared__ float t[32][33];
    int e = blockIdx.z;
    const float* I = in + (size_t)e*K*N;
    __half* O = outp + (size_t)e*N*K;
    int n0 = blockIdx.x*32, k0 = blockIdx.y*32;
    int tx = threadIdx.x, ty = threadIdx.y;
#pragma unroll
    for (int i = ty; i < 32; i += 8)
        t[i][tx] = I[(size_t)(k0+i)*N + n0 + tx];
    __syncthreads();
#pragma unroll
    for (int j = ty; j < 32; j += 8)
        O[(size_t)(n0+j)*K + k0 + tx] = __float2half(t[tx][j]);
}

// ---------------- routing: logits, top-2, softmax (fp32 exact) ----------------
__global__ void k_route(const float* __restrict__ x,
                        const float* __restrict__ Wg,
                        const float* __restrict__ bg) {
    int t = blockIdx.x;
    int tid = threadIdx.x;
    const float* xr = x + (size_t)t*DM;
    float acc[NE];
#pragma unroll
    for (int e = 0; e < NE; e++) acc[e] = 0.f;
    for (int i = tid; i < DM; i += 256) {
        float xv = xr[i];
#pragma unroll
        for (int e = 0; e < NE; e++) acc[e] += xv * Wg[i*NE + e];
    }
    __shared__ float s[NE][256];
#pragma unroll
    for (int e = 0; e < NE; e++) s[e][tid] = acc[e];
    __syncthreads();
    for (int off = 128; off > 0; off >>= 1) {
        if (tid < off) {
#pragma unroll
            for (int e = 0; e < NE; e++) s[e][tid] += s[e][tid + off];
        }
        __syncthreads();
    }
    if (tid == 0) {
        float v[NE];
#pragma unroll
        for (int e = 0; e < NE; e++) v[e] = s[e][0] + bg[e];
        int i0 = 0;
#pragma unroll
        for (int e = 1; e < NE; e++) if (v[e] > v[i0]) i0 = e;
        int i1 = (i0 == 0) ? 1 : 0;
#pragma unroll
        for (int e = 0; e < NE; e++) if (e != i0 && v[e] > v[i1]) i1 = e;
        float e1 = expf(v[i1] - v[i0]);
        float inv = 1.f / (1.f + e1);
        g_tok_e[2*t]   = i0;  g_tok_w[2*t]   = inv;
        g_tok_e[2*t+1] = i1;  g_tok_w[2*t+1] = e1 * inv;
        atomicAdd(&g_count[i0], 1);
        atomicAdd(&g_count[i1], 1);
    }
}

__global__ void k_scan() {
    int o = 0;
    for (int e = 0; e < NE; e++) {
        g_off[e] = o;
        g_cursor[e] = o;
        o += g_count[e];
    }
}

__global__ void k_assign() {
    int t = blockIdx.x*blockDim.x + threadIdx.x;
    if (t >= T_TOK) return;
#pragma unroll
    for (int k = 0; k < TOPK; k++) {
        int e = g_tok_e[2*t + k];
        int pos = atomicAdd(&g_cursor[e], 1);
        g_pair_tok[pos] = t;
        g_pair_w[pos]   = g_tok_w[2*t + k];
    }
}

// ================= pass A: act = (x@W0+b0)*silu(x@W1+b1) =================
// block 128M x 128N, KS=32, 2-stage cp.async, fp16 m16n8k16, ldmatrix frags.
// 512 threads = 16 warps (4x4), warp tile 32x32.
__global__ void __launch_bounds__(512,1) k_mlp1(const float* __restrict__ b0,
                                                const float* __restrict__ b1) {
    int e   = blockIdx.z;
    int cnt = g_count[e];
    int m0  = blockIdx.y * 128;
    if (m0 >= cnt) return;
    int off = g_off[e];
    int n0  = blockIdx.x * 128;

    const __half* B0g = g_w0h + (size_t)e*DM*DH;   // [n][k]
    const __half* B1g = g_w1h + (size_t)e*DM*DH;

    extern __shared__ __half sh[];
    __half* As  = sh;                    // [2][128][40]
    __half* Bs0 = As + 2*TILE_H;
    __half* Bs1 = Bs0 + 2*TILE_H;
    int*  toks = (int*)(Bs1 + 2*TILE_H);

    int tid = threadIdx.x;
    if (tid < 128) {
        int m = m0 + tid;
        toks[tid] = (m < cnt) ? g_pair_tok[off + m] : -1;
    }
    __syncthreads();

    // loaders: 128 rows x 4 chunks of 8 halfs; one (row,chunk) per thread
    int lrow = tid >> 2;
    int lch  = (tid & 3) * 8;
    int tok  = toks[lrow];
    const __half* asrc = g_xh + (size_t)(tok < 0 ? 0 : tok)*DM + lch;
    int asz = (tok < 0) ? 0 : 16;
    unsigned adst = sptr(As + lrow*HLD + lch);
    const __half* b0src = B0g + (size_t)(n0 + lrow)*DM + lch;
    const __half* b1src = B1g + (size_t)(n0 + lrow)*DM + lch;
    unsigned b0dst = sptr(Bs0 + lrow*HLD + lch);
    unsigned b1dst = sptr(Bs1 + lrow*HLD + lch);

    int lane = tid & 31, warp = tid >> 5;
    int wm = warp & 3, wn = warp >> 2;
    int g  = lane >> 2, tig = lane & 3;

    // ldmatrix lane addresses (byte offsets into current stage)
    unsigned smb = sptr(As);
    unsigned aLA  = smb + ((wm*32 + (lane & 15))*HLD + (lane >> 4)*8)*2;
    unsigned bRow = wn*32 + (lane & 7) + (lane >> 4)*8;
    unsigned bCol = ((lane >> 3) & 1)*8;
    unsigned b0LA = smb + 2*TILE_H*2 + (bRow*HLD + bCol)*2;
    unsigned b1LA = b0LA + 2*TILE_H*2;

    float ch[2][4][4], cg[2][4][4];
#pragma unroll
    for (int mi = 0; mi < 2; mi++)
#pragma unroll
        for (int ni = 0; ni < 4; ni++)
#pragma unroll
            for (int j = 0; j < 4; j++) { ch[mi][ni][j] = 0.f; cg[mi][ni][j] = 0.f; }

#define LOAD1(stage, kk0)  {                              \
        unsigned so = (stage)*TILE_H*2;                   \
        cp16(adst  + so, asrc  + (kk0), asz);             \
        cp16(b0dst + so, b0src + (kk0), 16);              \
        cp16(b1dst + so, b1src + (kk0), 16);              \
        cp_commit(); }

    LOAD1(0, 0);

    const int NK = DM / KS;
    for (int kt = 0; kt < NK; kt++) {
        int cur = kt & 1;
        cp_wait0();
        __syncthreads();
        if (kt + 1 < NK) LOAD1(cur ^ 1, (kt + 1)*KS);

        unsigned so = cur*(unsigned)(TILE_H*2);
#pragma unroll
        for (int ks = 0; ks < KS; ks += 16) {
            unsigned A0[4], A1[4], P0[4], P1[4], Q0[4], Q1[4];
            ldsm4(A0, aLA  + so + ks*2);
            ldsm4(A1, aLA  + so + ks*2 + 16*HLD*2);
            ldsm4(P0, b0LA + so + ks*2);
            ldsm4(P1, b0LA + so + ks*2 + 16*HLD*2);
            ldsm4(Q0, b1LA + so + ks*2);
            ldsm4(Q1, b1LA + so + ks*2 + 16*HLD*2);
            // ni0:(P0[0],P0[1]) ni1:(P0[2],P0[3]) ni2:(P1[0],P1[1]) ni3:(P1[2],P1[3])
            mma_f16(ch[0][0], A0[0],A0[1],A0[2],A0[3], P0[0],P0[1]);
            mma_f16(ch[1][0], A1[0],A1[1],A1[2],A1[3], P0[0],P0[1]);
            mma_f16(ch[0][1], A0[0],A0[1],A0[2],A0[3], P0[2],P0[3]);
            mma_f16(ch[1][1], A1[0],A1[1],A1[2],A1[3], P0[2],P0[3]);
            mma_f16(ch[0][2], A0[0],A0[1],A0[2],A0[3], P1[0],P1[1]);
            mma_f16(ch[1][2], A1[0],A1[1],A1[2],A1[3], P1[0],P1[1]);
            mma_f16(ch[0][3], A0[0],A0[1],A0[2],A0[3], P1[2],P1[3]);
            mma_f16(ch[1][3], A1[0],A1[1],A1[2],A1[3], P1[2],P1[3]);
            mma_f16(cg[0][0], A0[0],A0[1],A0[2],A0[3], Q0[0],Q0[1]);
            mma_f16(cg[1][0], A1[0],A1[1],A1[2],A1[3], Q0[0],Q0[1]);
            mma_f16(cg[0][1], A0[0],A0[1],A0[2],A0[3], Q0[2],Q0[3]);
            mma_f16(cg[1][1], A1[0],A1[1],A1[2],A1[3], Q0[2],Q0[3]);
            mma_f16(cg[0][2], A0[0],A0[1],A0[2],A0[3], Q1[0],Q1[1]);
            mma_f16(cg[1][2], A1[0],A1[1],A1[2],A1[3], Q1[0],Q1[1]);
            mma_f16(cg[0][3], A0[0],A0[1],A0[2],A0[3], Q1[2],Q1[3]);
            mma_f16(cg[1][3], A1[0],A1[1],A1[2],A1[3], Q1[2],Q1[3]);
        }
        __syncthreads();
    }

    const float* b0p = b0 + (size_t)e*DH;
    const float* b1p = b1 + (size_t)e*DH;
#pragma unroll
    for (int mi = 0; mi < 2; mi++) {
#pragma unroll
        for (int hh = 0; hh < 2; hh++) {
            int r = m0 + wm*32 + mi*16 + g + hh*8;
            if (r < cnt) {
                size_t row = (size_t)(off + r);
#pragma unroll
                for (int ni = 0; ni < 4; ni++) {
                    int c = n0 + wn*32 + ni*8 + tig*2;
                    float h0 = ch[mi][ni][hh*2+0] + b0p[c];
                    float g0 = cg[mi][ni][hh*2+0] + b1p[c];
                    float h1 = ch[mi][ni][hh*2+1] + b0p[c+1];
                    float g1 = cg[mi][ni][hh*2+1] + b1p[c+1];
                    float o0 = h0 * (g0 / (1.f + expf(-g0)));
                    float o1 = h1 * (g1 / (1.f + expf(-g1)));
                    *(__half2*)&g_acth[row*DH + c] = __floats2half2_rn(o0, o1);
                }
            }
        }
    }
}

// ================= pass B: out[token] += w * (act @ W2 + b2) =================
__global__ void __launch_bounds__(512,1) k_mlp2(const float* __restrict__ b2,
                                                float* __restrict__ out) {
    int e   = blockIdx.z;
    int cnt = g_count[e];
    int m0  = blockIdx.y * 128;
    if (m0 >= cnt) return;
    int off = g_off[e];
    int n0  = blockIdx.x * 128;

    const __half* Bg = g_w2h + (size_t)e*DH*DM;   // [n][k]

    extern __shared__ __half sh[];
    __half* As = sh;                  // [2][128][40]
    __half* Bs = As + 2*TILE_H;

    int tid = threadIdx.x;
    int lrow = tid >> 2;
    int lch  = (tid & 3) * 8;
    int m = m0 + lrow;
    int ok = (m < cnt);
    const __half* asrc = g_acth + (size_t)(ok ? (off + m) : 0)*DH + lch;
    int asz = ok ? 16 : 0;
    unsigned adst = sptr(As + lrow*HLD + lch);
    const __half* bsrc = Bg + (size_t)(n0 + lrow)*DH + lch;
    unsigned bdst = sptr(Bs + lrow*HLD + lch);

    int lane = tid & 31, warp = tid >> 5;
    int wm = warp & 3, wn = warp >> 2;
    int g  = lane >> 2, tig = lane & 3;

    unsigned smb = sptr(As);
    unsigned aLA  = smb + ((wm*32 + (lane & 15))*HLD + (lane >> 4)*8)*2;
    unsigned bRow = wn*32 + (lane & 7) + (lane >> 4)*8;
    unsigned bCol = ((lane >> 3) & 1)*8;
    unsigned bLA  = smb + 2*TILE_H*2 + (bRow*HLD + bCol)*2;

    float acc[2][4][4];
#pragma unroll
    for (int mi = 0; mi < 2; mi++)
#pragma unroll
        for (int ni = 0; ni < 4; ni++)
#pragma unroll
            for (int j = 0; j < 4; j++) acc[mi][ni][j] = 0.f;

#define LOAD2(stage, kk0)  {                              \
        unsigned so = (stage)*TILE_H*2;                   \
        cp16(adst + so, asrc + (kk0), asz);               \
        cp16(bdst + so, bsrc + (kk0), 16);                \
        cp_commit(); }

    LOAD2(0, 0);

    const int NK = DH / KS;
    for (int kt = 0; kt < NK; kt++) {
        int cur = kt & 1;
        cp_wait0();
        __syncthreads();
        if (kt + 1 < NK) LOAD2(cur ^ 1, (kt + 1)*KS);

        unsigned so = cur*(unsigned)(TILE_H*2);
#pragma unroll
        for (int ks = 0; ks < KS; ks += 16) {
            unsigned A0[4], A1[4], P0[4], P1[4];
            ldsm4(A0, aLA + so + ks*2);
            ldsm4(A1, aLA + so + ks*2 + 16*HLD*2);
            ldsm4(P0, bLA + so + ks*2);
            ldsm4(P1, bLA + so + ks*2 + 16*HLD*2);
            mma_f16(acc[0][0], A0[0],A0[1],A0[2],A0[3], P0[0],P0[1]);
            mma_f16(acc[1][0], A1[0],A1[1],A1[2],A1[3], P0[0],P0[1]);
            mma_f16(acc[0][1], A0[0],A0[1],A0[2],A0[3], P0[2],P0[3]);
            mma_f16(acc[1][1], A1[0],A1[1],A1[2],A1[3], P0[2],P0[3]);
            mma_f16(acc[0][2], A0[0],A0[1],A0[2],A0[3], P1[0],P1[1]);
            mma_f16(acc[1][2], A1[0],A1[1],A1[2],A1[3], P1[0],P1[1]);
            mma_f16(acc[0][3], A0[0],A0[1],A0[2],A0[3], P1[2],P1[3]);
            mma_f16(acc[1][3], A1[0],A1[1],A1[2],A1[3], P1[2],P1[3]);
        }
        __syncthreads();
    }

    const float* b2p = b2 + (size_t)e*DM;
#pragma unroll
    for (int mi = 0; mi < 2; mi++) {
#pragma unroll
        for (int hh = 0; hh < 2; hh++) {
            int r = m0 + wm*32 + mi*16 + g + hh*8;
            if (r < cnt) {
                int tokp = g_pair_tok[off + r];
                float w = g_pair_w[off + r];
                float* orow = out + (size_t)tokp*DM;
#pragma unroll
                for (int ni = 0; ni < 4; ni++) {
                    int c = n0 + wn*32 + ni*8 + tig*2;
                    atomicAdd(&orow[c],   w * (acc[mi][ni][hh*2+0] + b2p[c]));
                    atomicAdd(&orow[c+1], w * (acc[mi][ni][hh*2+1] + b2p[c+1]));
                }
            }
        }
    }
}

// ---------------- launch ----------------
#define SMEM1 (3*2*TILE_H*2 + 128*4)
#define SMEM2 (2*2*TILE_H*2)

extern "C" void kernel_launch(void* const* d_in, const int* in_sizes, int n_in,
                              void* d_out, int out_size) {
    const float* x  = (const float*)d_in[0];
    const float* Wg = (const float*)d_in[1];
    const float* bg = (const float*)d_in[2];
    const float* W0 = (const float*)d_in[3];
    const float* b0 = (const float*)d_in[4];
    const float* W1 = (const float*)d_in[5];
    const float* b1 = (const float*)d_in[6];
    const float* W2 = (const float*)d_in[7];
    const float* b2 = (const float*)d_in[8];
    float* out = (float*)d_out;

    static int smem_set = 0;
    if (!smem_set) {
        cudaFuncSetAttribute(k_mlp1, cudaFuncAttributeMaxDynamicSharedMemorySize, SMEM1);
        cudaFuncSetAttribute(k_mlp2, cudaFuncAttributeMaxDynamicSharedMemorySize, SMEM2);
        smem_set = 1;
    }

    __half* w0d; cudaGetSymbolAddress((void**)&w0d, g_w0h);
    __half* w1d; cudaGetSymbolAddress((void**)&w1d, g_w1h);
    __half* w2d; cudaGetSymbolAddress((void**)&w2d, g_w2h);
    __half* xd;  cudaGetSymbolAddress((void**)&xd,  g_xh);

    const int XN4 = T_TOK*DM/4;

    k_reset <<<(T_TOK*DM + 255)/256, 256>>>(out, T_TOK*DM);
    k_route <<<T_TOK, 256>>>(x, Wg, bg);
    k_scan  <<<1, 1>>>();
    k_assign<<<(T_TOK + 255)/256, 256>>>();
    k_cvtx  <<<(XN4 + 255)/256, 256>>>(x, xd, XN4);
    k_tw    <<<dim3(DH/32, DM/32, NE), dim3(32,8)>>>(W0, w0d, DM, DH);
    k_tw    <<<dim3(DH/32, DM/32, NE), dim3(32,8)>>>(W1, w1d, DM, DH);
    k_tw    <<<dim3(DM/32, DH/32, NE), dim3(32,8)>>>(W2, w2d, DH, DM);
    k_mlp1  <<<dim3(DH/128, 32, NE), 512, SMEM1>>>(b0, b1);
    k_mlp2  <<<dim3(DM/128, 32, NE), 512, SMEM2>>>(b2, out);
}

// round 9
// speedup vs baseline: 1.9235x; 1.0483x over previous
#include <cuda_runtime.h>
#include <cuda_fp16.h>
#include <math.h>

#define NE 8
#define TOPK 2
#define DM 1024
#define DH 4096
#define T_TOK 4096
#define NPAIR (T_TOK*TOPK)
#define KS 32          // k-tile in elements (halfs)
#define HLD 40         // smem row stride in halfs (padded)
#define TILE_H (128*HLD)   // halfs per tile buffer
#define NSTG 3

// ---------------- scratch (device globals; no allocation) ----------------
__device__ int    g_count[NE];
__device__ int    g_off[NE];
__device__ int    g_cursor[NE];
__device__ int    g_pair_tok[NPAIR];
__device__ float  g_pair_w[NPAIR];
__device__ int    g_tok_e[T_TOK*TOPK];
__device__ float  g_tok_w[T_TOK*TOPK];
__device__ __half g_acth[(size_t)NPAIR*DH];    // 64 MB fp16 activations
__device__ __half g_w0h[(size_t)NE*DM*DH];     // [e][n=DH][k=DM] fp16 transposed
__device__ __half g_w1h[(size_t)NE*DM*DH];
__device__ __half g_w2h[(size_t)NE*DH*DM];     // [e][n=DM][k=DH]
__device__ __half g_xh[(size_t)T_TOK*DM];      // fp16 activations

__device__ __forceinline__ void mma_f16(float c[4], unsigned a0, unsigned a1,
                                        unsigned a2, unsigned a3,
                                        unsigned b0, unsigned b1) {
    asm volatile(
        "mma.sync.aligned.m16n8k16.row.col.f32.f16.f16.f32 "
        "{%0,%1,%2,%3}, {%4,%5,%6,%7}, {%8,%9}, {%0,%1,%2,%3};\n"
        : "+f"(c[0]), "+f"(c[1]), "+f"(c[2]), "+f"(c[3])
        : "r"(a0), "r"(a1), "r"(a2), "r"(a3), "r"(b0), "r"(b1));
}

__device__ __forceinline__ void ldsm4(unsigned r[4], unsigned addr) {
    asm volatile("ldmatrix.sync.aligned.m8n8.x4.shared.b16 {%0,%1,%2,%3}, [%4];"
                 : "=r"(r[0]), "=r"(r[1]), "=r"(r[2]), "=r"(r[3]) : "r"(addr));
}

__device__ __forceinline__ unsigned sptr(const void* p) {
    return (unsigned)__cvta_generic_to_shared(p);
}
__device__ __forceinline__ void cp16(unsigned dst, const void* src, int srcbytes) {
    asm volatile("cp.async.cg.shared.global [%0], [%1], 16, %2;\n"
                 :: "r"(dst), "l"(src), "r"(srcbytes));
}
__device__ __forceinline__ void cp_commit() { asm volatile("cp.async.commit_group;\n"); }
__device__ __forceinline__ void cp_wait1()  { asm volatile("cp.async.wait_group 1;\n"); }

// ---------------- reset: zero output + counters ----------------
__global__ void k_reset(float* out, int n) {
    int i = blockIdx.x*blockDim.x + threadIdx.x;
    if (i < n) out[i] = 0.f;
    if (i < NE) g_count[i] = 0;
}

// ---------------- x -> fp16 ----------------
__global__ void k_cvtx(const float* __restrict__ in, __half* __restrict__ outp, int n4) {
    int i = blockIdx.x*blockDim.x + threadIdx.x;
    if (i < n4) {
        float4 v = ((const float4*)in)[i];
        ((__half2*)outp)[2*i]   = __floats2half2_rn(v.x, v.y);
        ((__half2*)outp)[2*i+1] = __floats2half2_rn(v.z, v.w);
    }
}

// ---------------- weight prep: transpose [k][n] -> [n][k], fp16 ----------------
__global__ void k_tw(const float* __restrict__ in, __half* __restrict__ outp,
                     int K, int N) {
    __shared__ float t[32][33];
    int e = blockIdx.z;
    const float* I = in + (size_t)e*K*N;
    __half* O = outp + (size_t)e*N*K;
    int n0 = blockIdx.x*32, k0 = blockIdx.y*32;
    int tx = threadIdx.x, ty = threadIdx.y;
#pragma unroll
    for (int i = ty; i < 32; i += 8)
        t[i][tx] = I[(size_t)(k0+i)*N + n0 + tx];
    __syncthreads();
#pragma unroll
    for (int j = ty; j < 32; j += 8)
        O[(size_t)(n0+j)*K + k0 + tx] = __float2half(t[tx][j]);
}

// ---------------- routing: logits, top-2, softmax (fp32 exact) ----------------
__global__ void k_route(const float* __restrict__ x,
                        const float* __restrict__ Wg,
                        const float* __restrict__ bg) {
    int t = blockIdx.x;
    int tid = threadIdx.x;
    const float* xr = x + (size_t)t*DM;
    float acc[NE];
#pragma unroll
    for (int e = 0; e < NE; e++) acc[e] = 0.f;
    for (int i = tid; i < DM; i += 256) {
        float xv = xr[i];
#pragma unroll
        for (int e = 0; e < NE; e++) acc[e] += xv * Wg[i*NE + e];
    }
    __shared__ float s[NE][256];
#pragma unroll
    for (int e = 0; e < NE; e++) s[e][tid] = acc[e];
    __syncthreads();
    for (int off = 128; off > 0; off >>= 1) {
        if (tid < off) {
#pragma unroll
            for (int e = 0; e < NE; e++) s[e][tid] += s[e][tid + off];
        }
        __syncthreads();
    }
    if (tid == 0) {
        float v[NE];
#pragma unroll
        for (int e = 0; e < NE; e++) v[e] = s[e][0] + bg[e];
        int i0 = 0;
#pragma unroll
        for (int e = 1; e < NE; e++) if (v[e] > v[i0]) i0 = e;
        int i1 = (i0 == 0) ? 1 : 0;
#pragma unroll
        for (int e = 0; e < NE; e++) if (e != i0 && v[e] > v[i1]) i1 = e;
        float e1 = expf(v[i1] - v[i0]);
        float inv = 1.f / (1.f + e1);
        g_tok_e[2*t]   = i0;  g_tok_w[2*t]   = inv;
        g_tok_e[2*t+1] = i1;  g_tok_w[2*t+1] = e1 * inv;
        atomicAdd(&g_count[i0], 1);
        atomicAdd(&g_count[i1], 1);
    }
}

__global__ void k_scan() {
    int o = 0;
    for (int e = 0; e < NE; e++) {
        g_off[e] = o;
        g_cursor[e] = o;
        o += g_count[e];
    }
}

__global__ void k_assign() {
    int t = blockIdx.x*blockDim.x + threadIdx.x;
    if (t >= T_TOK) return;
#pragma unroll
    for (int k = 0; k < TOPK; k++) {
        int e = g_tok_e[2*t + k];
        int pos = atomicAdd(&g_cursor[e], 1);
        g_pair_tok[pos] = t;
        g_pair_w[pos]   = g_tok_w[2*t + k];
    }
}

// ================= pass A: act = (x@W0+b0)*silu(x@W1+b1) =================
// block 128M x 128N, KS=32, 3-stage cp.async (empty-commit drain), ldmatrix.
// 512 threads = 16 warps (4x4), warp tile 32x32.
__global__ void __launch_bounds__(512,1) k_mlp1(const float* __restrict__ b0,
                                                const float* __restrict__ b1) {
    int e   = blockIdx.z;
    int cnt = g_count[e];
    int m0  = blockIdx.y * 128;
    if (m0 >= cnt) return;
    int off = g_off[e];
    int n0  = blockIdx.x * 128;

    const __half* B0g = g_w0h + (size_t)e*DM*DH;   // [n][k]
    const __half* B1g = g_w1h + (size_t)e*DM*DH;

    extern __shared__ __half sh[];
    __half* As  = sh;                     // [3][128][40]
    __half* Bs0 = As + NSTG*TILE_H;
    __half* Bs1 = Bs0 + NSTG*TILE_H;
    int*  toks = (int*)(Bs1 + NSTG*TILE_H);

    int tid = threadIdx.x;
    if (tid < 128) {
        int m = m0 + tid;
        toks[tid] = (m < cnt) ? g_pair_tok[off + m] : -1;
    }
    __syncthreads();

    // loaders: 128 rows x 4 chunks of 8 halfs; one (row,chunk) per thread
    int lrow = tid >> 2;
    int lch  = (tid & 3) * 8;
    int tok  = toks[lrow];
    const __half* asrc = g_xh + (size_t)(tok < 0 ? 0 : tok)*DM + lch;
    int asz = (tok < 0) ? 0 : 16;
    unsigned adst = sptr(As + lrow*HLD + lch);
    const __half* b0src = B0g + (size_t)(n0 + lrow)*DM + lch;
    const __half* b1src = B1g + (size_t)(n0 + lrow)*DM + lch;
    unsigned b0dst = sptr(Bs0 + lrow*HLD + lch);
    unsigned b1dst = sptr(Bs1 + lrow*HLD + lch);

    int lane = tid & 31, warp = tid >> 5;
    int wm = warp & 3, wn = warp >> 2;
    int g  = lane >> 2, tig = lane & 3;

    // ldmatrix lane addresses (byte offsets into current stage)
    unsigned smb = sptr(As);
    unsigned aLA  = smb + ((wm*32 + (lane & 15))*HLD + (lane >> 4)*8)*2;
    unsigned bRow = wn*32 + (lane & 7) + (lane >> 4)*8;
    unsigned bCol = ((lane >> 3) & 1)*8;
    unsigned b0LA = smb + NSTG*TILE_H*2 + (bRow*HLD + bCol)*2;
    unsigned b1LA = b0LA + NSTG*TILE_H*2;

    float ch[2][4][4], cg[2][4][4];
#pragma unroll
    for (int mi = 0; mi < 2; mi++)
#pragma unroll
        for (int ni = 0; ni < 4; ni++)
#pragma unroll
            for (int j = 0; j < 4; j++) { ch[mi][ni][j] = 0.f; cg[mi][ni][j] = 0.f; }

#define LOAD1(stage, kk0)  {                              \
        unsigned so = (stage)*TILE_H*2;                   \
        cp16(adst  + so, asrc  + (kk0), asz);             \
        cp16(b0dst + so, b0src + (kk0), 16);              \
        cp16(b1dst + so, b1src + (kk0), 16);              \
        cp_commit(); }

    LOAD1(0, 0);
    LOAD1(1, KS);

    const int NK = DM / KS;
    for (int kt = 0; kt < NK; kt++) {
        int cur = kt % NSTG;
        cp_wait1();
        __syncthreads();
        if (kt + 2 < NK) { LOAD1((kt + 2) % NSTG, (kt + 2)*KS); }
        else             { cp_commit(); }   // empty group: keeps wait_group 1 draining

        unsigned so = cur*(unsigned)(TILE_H*2);
#pragma unroll
        for (int ks = 0; ks < KS; ks += 16) {
            unsigned A0[4], A1[4], P0[4], P1[4], Q0[4], Q1[4];
            ldsm4(A0, aLA  + so + ks*2);
            ldsm4(A1, aLA  + so + ks*2 + 16*HLD*2);
            ldsm4(P0, b0LA + so + ks*2);
            ldsm4(P1, b0LA + so + ks*2 + 16*HLD*2);
            ldsm4(Q0, b1LA + so + ks*2);
            ldsm4(Q1, b1LA + so + ks*2 + 16*HLD*2);
            mma_f16(ch[0][0], A0[0],A0[1],A0[2],A0[3], P0[0],P0[1]);
            mma_f16(ch[1][0], A1[0],A1[1],A1[2],A1[3], P0[0],P0[1]);
            mma_f16(ch[0][1], A0[0],A0[1],A0[2],A0[3], P0[2],P0[3]);
            mma_f16(ch[1][1], A1[0],A1[1],A1[2],A1[3], P0[2],P0[3]);
            mma_f16(ch[0][2], A0[0],A0[1],A0[2],A0[3], P1[0],P1[1]);
            mma_f16(ch[1][2], A1[0],A1[1],A1[2],A1[3], P1[0],P1[1]);
            mma_f16(ch[0][3], A0[0],A0[1],A0[2],A0[3], P1[2],P1[3]);
            mma_f16(ch[1][3], A1[0],A1[1],A1[2],A1[3], P1[2],P1[3]);
            mma_f16(cg[0][0], A0[0],A0[1],A0[2],A0[3], Q0[0],Q0[1]);
            mma_f16(cg[1][0], A1[0],A1[1],A1[2],A1[3], Q0[0],Q0[1]);
            mma_f16(cg[0][1], A0[0],A0[1],A0[2],A0[3], Q0[2],Q0[3]);
            mma_f16(cg[1][1], A1[0],A1[1],A1[2],A1[3], Q0[2],Q0[3]);
            mma_f16(cg[0][2], A0[0],A0[1],A0[2],A0[3], Q1[0],Q1[1]);
            mma_f16(cg[1][2], A1[0],A1[1],A1[2],A1[3], Q1[0],Q1[1]);
            mma_f16(cg[0][3], A0[0],A0[1],A0[2],A0[3], Q1[2],Q1[3]);
            mma_f16(cg[1][3], A1[0],A1[1],A1[2],A1[3], Q1[2],Q1[3]);
        }
    }

    const float* b0p = b0 + (size_t)e*DH;
    const float* b1p = b1 + (size_t)e*DH;
#pragma unroll
    for (int mi = 0; mi < 2; mi++) {
#pragma unroll
        for (int hh = 0; hh < 2; hh++) {
            int r = m0 + wm*32 + mi*16 + g + hh*8;
            if (r < cnt) {
                size_t row = (size_t)(off + r);
#pragma unroll
                for (int ni = 0; ni < 4; ni++) {
                    int c = n0 + wn*32 + ni*8 + tig*2;
                    float h0 = ch[mi][ni][hh*2+0] + b0p[c];
                    float g0 = cg[mi][ni][hh*2+0] + b1p[c];
                    float h1 = ch[mi][ni][hh*2+1] + b0p[c+1];
                    float g1 = cg[mi][ni][hh*2+1] + b1p[c+1];
                    float o0 = h0 * (g0 / (1.f + expf(-g0)));
                    float o1 = h1 * (g1 / (1.f + expf(-g1)));
                    *(__half2*)&g_acth[row*DH + c] = __floats2half2_rn(o0, o1);
                }
            }
        }
    }
}

// ================= pass B: out[token] += w * (act @ W2 + b2) =================
__global__ void __launch_bounds__(512,1) k_mlp2(const float* __restrict__ b2,
                                                float* __restrict__ out) {
    int e   = blockIdx.z;
    int cnt = g_count[e];
    int m0  = blockIdx.y * 128;
    if (m0 >= cnt) return;
    int off = g_off[e];
    int n0  = blockIdx.x * 128;

    const __half* Bg = g_w2h + (size_t)e*DH*DM;   // [n][k]

    extern __shared__ __half sh[];
    __half* As = sh;                   // [3][128][40]
    __half* Bs = As + NSTG*TILE_H;

    int tid = threadIdx.x;
    int lrow = tid >> 2;
    int lch  = (tid & 3) * 8;
    int m = m0 + lrow;
    int ok = (m < cnt);
    const __half* asrc = g_acth + (size_t)(ok ? (off + m) : 0)*DH + lch;
    int asz = ok ? 16 : 0;
    unsigned adst = sptr(As + lrow*HLD + lch);
    const __half* bsrc = Bg + (size_t)(n0 + lrow)*DH + lch;
    unsigned bdst = sptr(Bs + lrow*HLD + lch);

    int lane = tid & 31, warp = tid >> 5;
    int wm = warp & 3, wn = warp >> 2;
    int g  = lane >> 2, tig = lane & 3;

    unsigned smb = sptr(As);
    unsigned aLA  = smb + ((wm*32 + (lane & 15))*HLD + (lane >> 4)*8)*2;
    unsigned bRow = wn*32 + (lane & 7) + (lane >> 4)*8;
    unsigned bCol = ((lane >> 3) & 1)*8;
    unsigned bLA  = smb + NSTG*TILE_H*2 + (bRow*HLD + bCol)*2;

    float acc[2][4][4];
#pragma unroll
    for (int mi = 0; mi < 2; mi++)
#pragma unroll
        for (int ni = 0; ni < 4; ni++)
#pragma unroll
            for (int j = 0; j < 4; j++) acc[mi][ni][j] = 0.f;

#define LOAD2(stage, kk0)  {                              \
        unsigned so = (stage)*TILE_H*2;                   \
        cp16(adst + so, asrc + (kk0), asz);               \
        cp16(bdst + so, bsrc + (kk0), 16);                \
        cp_commit(); }

    LOAD2(0, 0);
    LOAD2(1, KS);

    const int NK = DH / KS;
    for (int kt = 0; kt < NK; kt++) {
        int cur = kt % NSTG;
        cp_wait1();
        __syncthreads();
        if (kt + 2 < NK) { LOAD2((kt + 2) % NSTG, (kt + 2)*KS); }
        else             { cp_commit(); }   // empty group drain

        unsigned so = cur*(unsigned)(TILE_H*2);
#pragma unroll
        for (int ks = 0; ks < KS; ks += 16) {
            unsigned A0[4], A1[4], P0[4], P1[4];
            ldsm4(A0, aLA + so + ks*2);
            ldsm4(A1, aLA + so + ks*2 + 16*HLD*2);
            ldsm4(P0, bLA + so + ks*2);
            ldsm4(P1, bLA + so + ks*2 + 16*HLD*2);
            mma_f16(acc[0][0], A0[0],A0[1],A0[2],A0[3], P0[0],P0[1]);
            mma_f16(acc[1][0], A1[0],A1[1],A1[2],A1[3], P0[0],P0[1]);
            mma_f16(acc[0][1], A0[0],A0[1],A0[2],A0[3], P0[2],P0[3]);
            mma_f16(acc[1][1], A1[0],A1[1],A1[2],A1[3], P0[2],P0[3]);
            mma_f16(acc[0][2], A0[0],A0[1],A0[2],A0[3], P1[0],P1[1]);
            mma_f16(acc[1][2], A1[0],A1[1],A1[2],A1[3], P1[0],P1[1]);
            mma_f16(acc[0][3], A0[0],A0[1],A0[2],A0[3], P1[2],P1[3]);
            mma_f16(acc[1][3], A1[0],A1[1],A1[2],A1[3], P1[2],P1[3]);
        }
    }

    const float* b2p = b2 + (size_t)e*DM;
#pragma unroll
    for (int mi = 0; mi < 2; mi++) {
#pragma unroll
        for (int hh = 0; hh < 2; hh++) {
            int r = m0 + wm*32 + mi*16 + g + hh*8;
            if (r < cnt) {
                int tokp = g_pair_tok[off + r];
                float w = g_pair_w[off + r];
                float* orow = out + (size_t)tokp*DM;
#pragma unroll
                for (int ni = 0; ni < 4; ni++) {
                    int c = n0 + wn*32 + ni*8 + tig*2;
                    atomicAdd(&orow[c],   w * (acc[mi][ni][hh*2+0] + b2p[c]));
                    atomicAdd(&orow[c+1], w * (acc[mi][ni][hh*2+1] + b2p[c+1]));
                }
            }
        }
    }
}

// ---------------- launch ----------------
#define SMEM1 (3*NSTG*TILE_H*2 + 128*4)
#define SMEM2 (2*NSTG*TILE_H*2)

extern "C" void kernel_launch(void* const* d_in, const int* in_sizes, int n_in,
                              void* d_out, int out_size) {
    const float* x  = (const float*)d_in[0];
    const float* Wg = (const float*)d_in[1];
    const float* bg = (const float*)d_in[2];
    const float* W0 = (const float*)d_in[3];
    const float* b0 = (const float*)d_in[4];
    const float* W1 = (const float*)d_in[5];
    const float* b1 = (const float*)d_in[6];
    const float* W2 = (const float*)d_in[7];
    const float* b2 = (const float*)d_in[8];
    float* out = (float*)d_out;

    static int smem_set = 0;
    if (!smem_set) {
        cudaFuncSetAttribute(k_mlp1, cudaFuncAttributeMaxDynamicSharedMemorySize, SMEM1);
        cudaFuncSetAttribute(k_mlp2, cudaFuncAttributeMaxDynamicSharedMemorySize, SMEM2);
        smem_set = 1;
    }

    __half* w0d; cudaGetSymbolAddress((void**)&w0d, g_w0h);
    __half* w1d; cudaGetSymbolAddress((void**)&w1d, g_w1h);
    __half* w2d; cudaGetSymbolAddress((void**)&w2d, g_w2h);
    __half* xd;  cudaGetSymbolAddress((void**)&xd,  g_xh);

    const int XN4 = T_TOK*DM/4;

    k_reset <<<(T_TOK*DM + 255)/256, 256>>>(out, T_TOK*DM);
    k_route <<<T_TOK, 256>>>(x, Wg, bg);
    k_scan  <<<1, 1>>>();
    k_assign<<<(T_TOK + 255)/256, 256>>>();
    k_cvtx  <<<(XN4 + 255)/256, 256>>>(x, xd, XN4);
    k_tw    <<<dim3(DH/32, DM/32, NE), dim3(32,8)>>>(W0, w0d, DM, DH);
    k_tw    <<<dim3(DH/32, DM/32, NE), dim3(32,8)>>>(W1, w1d, DM, DH);
    k_tw    <<<dim3(DM/32, DH/32, NE), dim3(32,8)>>>(W2, w2d, DH, DM);
    k_mlp1  <<<dim3(DH/128, 32, NE), 512, SMEM1>>>(b0, b1);
    k_mlp2  <<<dim3(DM/128, 32, NE), 512, SMEM2>>>(b2, out);
}